// round 1
// baseline (speedup 1.0000x reference)
#include <cuda_runtime.h>

#define U_CNT 100000
#define I_CNT 50000
#define N_CNT 150000
#define DIM   64
#define NNZ_CNT 3200000
#define B_CNT 4096

// Scratch: layer outputs (allocation-free rule -> __device__ globals)
__device__ __align__(16) float g_cur1[N_CNT * DIM];
__device__ __align__(16) float g_cur2[N_CNT * DIM];
__device__ __align__(16) float g_cur3[N_CNT * DIM];

__device__ __forceinline__ void red_add_v4(float* addr, float4 v) {
    asm volatile("red.global.add.v4.f32 [%0], {%1, %2, %3, %4};"
                 :: "l"(addr), "f"(v.x), "f"(v.y), "f"(v.z), "f"(v.w)
                 : "memory");
}

// Zero all three layer buffers in one pass.
__global__ void zero_bufs_kernel() {
    unsigned t = blockIdx.x * blockDim.x + threadIdx.x;
    const unsigned n4 = (unsigned)N_CNT * DIM / 4;  // 2.4M float4 per buffer
    if (t < n4) {
        float4 z = make_float4(0.f, 0.f, 0.f, 0.f);
        reinterpret_cast<float4*>(g_cur1)[t] = z;
        reinterpret_cast<float4*>(g_cur2)[t] = z;
        reinterpret_cast<float4*>(g_cur3)[t] = z;
    }
}

// First SPMM: x = concat(user_emb, item_emb) read directly from the two inputs.
__global__ void spmm_first_kernel(const int* __restrict__ rows,
                                  const int* __restrict__ cols,
                                  const float* __restrict__ vals,
                                  const float* __restrict__ ue,
                                  const float* __restrict__ ie,
                                  float* __restrict__ y) {
    unsigned t = blockIdx.x * blockDim.x + threadIdx.x;
    unsigned e = t >> 4;           // edge index
    if (e >= NNZ_CNT) return;
    int chunk = t & 15;            // 16 x float4 chunks per 64-float row
    int c = __ldg(cols + e);
    int r = __ldg(rows + e);
    float v = __ldg(vals + e);
    const float4* src = (c < U_CNT)
        ? reinterpret_cast<const float4*>(ue) + (size_t)c * 16
        : reinterpret_cast<const float4*>(ie) + (size_t)(c - U_CNT) * 16;
    float4 xv = __ldg(src + chunk);
    float4 o = make_float4(xv.x * v, xv.y * v, xv.z * v, xv.w * v);
    red_add_v4(y + (size_t)r * DIM + chunk * 4, o);
}

// Generic SPMM: y += A * x  (y pre-zeroed)
__global__ void spmm_kernel(const int* __restrict__ rows,
                            const int* __restrict__ cols,
                            const float* __restrict__ vals,
                            const float* __restrict__ x,
                            float* __restrict__ y) {
    unsigned t = blockIdx.x * blockDim.x + threadIdx.x;
    unsigned e = t >> 4;
    if (e >= NNZ_CNT) return;
    int chunk = t & 15;
    int c = __ldg(cols + e);
    int r = __ldg(rows + e);
    float v = __ldg(vals + e);
    float4 xv = __ldg(reinterpret_cast<const float4*>(x) + (size_t)c * 16 + chunk);
    float4 o = make_float4(xv.x * v, xv.y * v, xv.z * v, xv.w * v);
    red_add_v4(y + (size_t)r * DIM + chunk * 4, o);
}

// Epilogue: one block per batch element, 128 threads (half user, half item).
// out layout: [p_u (B*64) | u_target (B*64) | p_i (B*64) | i_target (B*64)]
__global__ void finalize_kernel(const float* __restrict__ ue,
                                const float* __restrict__ ie,
                                const float* __restrict__ W,
                                const float* __restrict__ bias,
                                const int* __restrict__ users,
                                const int* __restrict__ items,
                                const float* __restrict__ u_his,
                                const float* __restrict__ i_his,
                                float* __restrict__ out) {
    __shared__ float sWt[DIM * DIM];   // W transposed: sWt[k*64 + j] = W[j*64 + k]
    __shared__ float s_on[2][DIM];

    int b = blockIdx.x;
    int tid = threadIdx.x;  // 0..127

    // Cooperative transposed load of W (16 KB)
    for (int idx = tid; idx < DIM * DIM; idx += 128) {
        int j = idx >> 6, k = idx & 63;
        sWt[k * DIM + j] = W[idx];
    }

    int half = tid >> 6;         // 0 = user side, 1 = item side
    int j = tid & 63;
    int row = half ? __ldg(items + b) : __ldg(users + b);
    int node = half ? (U_CNT + row) : row;
    const float* base = half ? ie : ue;

    size_t gi = (size_t)row * DIM + j;
    size_t ni = (size_t)node * DIM + j;
    float on = 0.25f * (base[gi] + g_cur1[ni] + g_cur2[ni] + g_cur3[ni]);
    s_on[half][j] = on;
    __syncthreads();

    float acc = __ldg(bias + j);
    const float* onv = s_on[half];
    #pragma unroll
    for (int k = 0; k < DIM; k++)
        acc = fmaf(onv[k], sWt[k * DIM + j], acc);

    const float* his = half ? i_his : u_his;
    float tgt = his[gi] * 0.05f + on * 0.95f;

    size_t seg = (size_t)B_CNT * DIM;
    out[(size_t)(half * 2) * seg + (size_t)b * DIM + j] = acc;       // p_u / p_i
    out[(size_t)(half * 2 + 1) * seg + (size_t)b * DIM + j] = tgt;   // u_target / i_target
}

extern "C" void kernel_launch(void* const* d_in, const int* in_sizes, int n_in,
                              void* d_out, int out_size) {
    const float* ue    = (const float*)d_in[0];   // user_emb (U, 64)
    const float* ie    = (const float*)d_in[1];   // item_emb (I, 64)
    const float* W     = (const float*)d_in[2];   // (64, 64)
    const float* bias  = (const float*)d_in[3];   // (64,)
    const int*   rows  = (const int*)d_in[4];     // adj_rows (NNZ,)
    const int*   cols  = (const int*)d_in[5];     // adj_cols (NNZ,)
    const float* vals  = (const float*)d_in[6];   // adj_vals (NNZ,)
    const int*   users = (const int*)d_in[7];     // (B,)
    const int*   items = (const int*)d_in[8];     // (B,)
    const float* u_his = (const float*)d_in[9];   // (U, 64)
    const float* i_his = (const float*)d_in[10];  // (I, 64)
    float* out = (float*)d_out;

    // Device-global scratch addresses (resolved host-side; no allocation)
    float *c1, *c2, *c3;
    cudaGetSymbolAddress((void**)&c1, g_cur1);
    cudaGetSymbolAddress((void**)&c2, g_cur2);
    cudaGetSymbolAddress((void**)&c3, g_cur3);

    // 1. zero layer buffers
    {
        unsigned n4 = (unsigned)N_CNT * DIM / 4;
        zero_bufs_kernel<<<(n4 + 255) / 256, 256>>>();
    }

    // 2. three SPMM layers
    unsigned spmm_threads = (unsigned)NNZ_CNT * 16;
    unsigned spmm_blocks = (spmm_threads + 255) / 256;
    spmm_first_kernel<<<spmm_blocks, 256>>>(rows, cols, vals, ue, ie, c1);
    spmm_kernel<<<spmm_blocks, 256>>>(rows, cols, vals, c1, c2);
    spmm_kernel<<<spmm_blocks, 256>>>(rows, cols, vals, c2, c3);

    // 3. epilogue: gathers + momentum targets + 64x64 projection
    finalize_kernel<<<B_CNT, 128>>>(ue, ie, W, bias, users, items, u_his, i_his, out);
}

// round 2
// speedup vs baseline: 1.2386x; 1.2386x over previous
#include <cuda_runtime.h>

#define U_CNT 100000
#define I_CNT 50000
#define N_CNT 150000
#define DIM   64
#define NNZ_CNT 3200000
#define B_CNT 4096
#define NBW   ((N_CNT + 31) / 32)   // bitmap words

// ---- scratch (__device__ globals; allocation-free rule) ----
__device__ __align__(16) float g_cur1[N_CNT * DIM];
__device__ __align__(16) float g_cur2[N_CNT * DIM];
__device__ __align__(16) float g_cur3[N_CNT * DIM];

__device__ unsigned g_s3_bits[NBW];   // sampled nodes
__device__ unsigned g_s2_bits[NBW];   // nodes whose c2 is actually read
__device__ unsigned g_cnt3;
__device__ unsigned g_cnt2;

// compacted edge lists (worst case = full NNZ)
__device__ int   g_l3_r[NNZ_CNT];
__device__ int   g_l3_c[NNZ_CNT];
__device__ float g_l3_v[NNZ_CNT];
__device__ int   g_l2_r[NNZ_CNT];
__device__ int   g_l2_c[NNZ_CNT];
__device__ float g_l2_v[NNZ_CNT];

__device__ __forceinline__ void red_add_v4(float* addr, float4 v) {
    asm volatile("red.global.add.v4.f32 [%0], {%1, %2, %3, %4};"
                 :: "l"(addr), "f"(v.x), "f"(v.y), "f"(v.z), "f"(v.w)
                 : "memory");
}

__device__ __forceinline__ bool test_bit(const unsigned* bits, int n) {
    return (__ldg(bits + (n >> 5)) >> (n & 31)) & 1u;
}

// ---- 1. zero c1, c2, bitmaps, counters ----
__global__ void zero_main_kernel() {
    unsigned t = blockIdx.x * blockDim.x + threadIdx.x;
    const unsigned n4 = (unsigned)N_CNT * DIM / 4;  // 2.4M float4 per buffer
    if (t < n4) {
        float4 z = make_float4(0.f, 0.f, 0.f, 0.f);
        reinterpret_cast<float4*>(g_cur1)[t] = z;
        reinterpret_cast<float4*>(g_cur2)[t] = z;
    }
    if (t < NBW) { g_s3_bits[t] = 0u; g_s2_bits[t] = 0u; }
    if (t == 0) { g_cnt3 = 0u; g_cnt2 = 0u; }
}

// ---- 2. zero c3 at sampled rows only + build S3 (and seed S2) ----
__global__ void prep_sampled_kernel(const int* __restrict__ users,
                                    const int* __restrict__ items) {
    int b = blockIdx.x;              // 0..B-1
    int tid = threadIdx.x;           // 0..127
    int half = tid >> 6;             // 0 = user, 1 = item
    int j = tid & 63;
    int row = half ? __ldg(items + b) : __ldg(users + b);
    int node = half ? (U_CNT + row) : row;
    g_cur3[(size_t)node * DIM + j] = 0.f;
    if (j == 0) {
        atomicOr(&g_s3_bits[node >> 5], 1u << (node & 31));
        atomicOr(&g_s2_bits[node >> 5], 1u << (node & 31));
    }
}

// warp-aggregated append of (r,c,v) into a list
__device__ __forceinline__ void wagg_append(bool pred, int r, int c, float v,
                                            unsigned* cnt, int* lr, int* lc, float* lv) {
    unsigned mask = __ballot_sync(0xffffffffu, pred);
    if (pred) {
        int lane = threadIdx.x & 31;
        int leader = __ffs(mask) - 1;
        unsigned base = 0;
        if (lane == leader) base = atomicAdd(cnt, (unsigned)__popc(mask));
        base = __shfl_sync(mask, base, leader);
        unsigned pos = base + __popc(mask & ((1u << lane) - 1u));
        lr[pos] = r; lc[pos] = c; lv[pos] = v;
    }
}

// ---- 3. pass B: compact layer-3 edges (row in S3), mark S2 with their cols ----
__global__ void passB_kernel(const int* __restrict__ rows,
                             const int* __restrict__ cols,
                             const float* __restrict__ vals) {
    unsigned e = blockIdx.x * blockDim.x + threadIdx.x;
    bool pred = false;
    int r = 0, c = 0; float v = 0.f;
    if (e < NNZ_CNT) {
        r = __ldg(rows + e);
        if (test_bit(g_s3_bits, r)) {
            c = __ldg(cols + e);
            v = __ldg(vals + e);
            pred = true;
            atomicOr(&g_s2_bits[c >> 5], 1u << (c & 31));
        }
    }
    wagg_append(pred, r, c, v, &g_cnt3, g_l3_r, g_l3_c, g_l3_v);
}

// ---- 4. pass C: compact layer-2 edges (row in S2) ----
__global__ void passC_kernel(const int* __restrict__ rows,
                             const int* __restrict__ cols,
                             const float* __restrict__ vals) {
    unsigned e = blockIdx.x * blockDim.x + threadIdx.x;
    bool pred = false;
    int r = 0, c = 0; float v = 0.f;
    if (e < NNZ_CNT) {
        r = __ldg(rows + e);
        if (test_bit(g_s2_bits, r)) {
            c = __ldg(cols + e);
            v = __ldg(vals + e);
            pred = true;
        }
    }
    wagg_append(pred, r, c, v, &g_cnt2, g_l2_r, g_l2_c, g_l2_v);
}

// ---- 5. layer-1 SPMM: full edge set, x = concat(user_emb, item_emb) ----
__global__ void spmm_first_kernel(const int* __restrict__ rows,
                                  const int* __restrict__ cols,
                                  const float* __restrict__ vals,
                                  const float* __restrict__ ue,
                                  const float* __restrict__ ie,
                                  float* __restrict__ y) {
    unsigned t = blockIdx.x * blockDim.x + threadIdx.x;
    unsigned e = t >> 4;
    if (e >= NNZ_CNT) return;
    int chunk = t & 15;
    int c = __ldg(cols + e);
    int r = __ldg(rows + e);
    float v = __ldg(vals + e);
    const float4* src = (c < U_CNT)
        ? reinterpret_cast<const float4*>(ue) + (size_t)c * 16
        : reinterpret_cast<const float4*>(ie) + (size_t)(c - U_CNT) * 16;
    float4 xv = __ldg(src + chunk);
    float4 o = make_float4(xv.x * v, xv.y * v, xv.z * v, xv.w * v);
    red_add_v4(y + (size_t)r * DIM + chunk * 4, o);
}

// ---- 6./7. filtered SPMM over a compacted list (persistent grid-stride) ----
__global__ void spmm_list_kernel(const int* __restrict__ lr,
                                 const int* __restrict__ lc,
                                 const float* __restrict__ lv,
                                 const unsigned* __restrict__ cnt_ptr,
                                 const float* __restrict__ x,
                                 float* __restrict__ y) {
    unsigned total = __ldg(cnt_ptr) * 16u;
    unsigned stride = gridDim.x * blockDim.x;
    for (unsigned i = blockIdx.x * blockDim.x + threadIdx.x; i < total; i += stride) {
        unsigned e = i >> 4;
        int chunk = i & 15;
        int c = __ldg(lc + e);
        int r = __ldg(lr + e);
        float v = __ldg(lv + e);
        float4 xv = __ldg(reinterpret_cast<const float4*>(x) + (size_t)c * 16 + chunk);
        float4 o = make_float4(xv.x * v, xv.y * v, xv.z * v, xv.w * v);
        red_add_v4(y + (size_t)r * DIM + chunk * 4, o);
    }
}

// ---- 8. epilogue ----
__global__ void finalize_kernel(const float* __restrict__ ue,
                                const float* __restrict__ ie,
                                const float* __restrict__ W,
                                const float* __restrict__ bias,
                                const int* __restrict__ users,
                                const int* __restrict__ items,
                                const float* __restrict__ u_his,
                                const float* __restrict__ i_his,
                                float* __restrict__ out) {
    __shared__ float sWt[DIM * DIM];
    __shared__ float s_on[2][DIM];

    int b = blockIdx.x;
    int tid = threadIdx.x;  // 0..127

    for (int idx = tid; idx < DIM * DIM; idx += 128) {
        int j = idx >> 6, k = idx & 63;
        sWt[k * DIM + j] = W[idx];
    }

    int half = tid >> 6;
    int j = tid & 63;
    int row = half ? __ldg(items + b) : __ldg(users + b);
    int node = half ? (U_CNT + row) : row;
    const float* base = half ? ie : ue;

    size_t gi = (size_t)row * DIM + j;
    size_t ni = (size_t)node * DIM + j;
    float on = 0.25f * (base[gi] + g_cur1[ni] + g_cur2[ni] + g_cur3[ni]);
    s_on[half][j] = on;
    __syncthreads();

    float acc = __ldg(bias + j);
    const float* onv = s_on[half];
    #pragma unroll
    for (int k = 0; k < DIM; k++)
        acc = fmaf(onv[k], sWt[k * DIM + j], acc);

    const float* his = half ? i_his : u_his;
    float tgt = his[gi] * 0.05f + on * 0.95f;

    size_t seg = (size_t)B_CNT * DIM;
    out[(size_t)(half * 2) * seg + (size_t)b * DIM + j] = acc;
    out[(size_t)(half * 2 + 1) * seg + (size_t)b * DIM + j] = tgt;
}

extern "C" void kernel_launch(void* const* d_in, const int* in_sizes, int n_in,
                              void* d_out, int out_size) {
    const float* ue    = (const float*)d_in[0];
    const float* ie    = (const float*)d_in[1];
    const float* W     = (const float*)d_in[2];
    const float* bias  = (const float*)d_in[3];
    const int*   rows  = (const int*)d_in[4];
    const int*   cols  = (const int*)d_in[5];
    const float* vals  = (const float*)d_in[6];
    const int*   users = (const int*)d_in[7];
    const int*   items = (const int*)d_in[8];
    const float* u_his = (const float*)d_in[9];
    const float* i_his = (const float*)d_in[10];
    float* out = (float*)d_out;

    float *c1, *c2, *c3;
    cudaGetSymbolAddress((void**)&c1, g_cur1);
    cudaGetSymbolAddress((void**)&c2, g_cur2);
    cudaGetSymbolAddress((void**)&c3, g_cur3);
    unsigned *cnt3, *cnt2;
    cudaGetSymbolAddress((void**)&cnt3, g_cnt3);
    cudaGetSymbolAddress((void**)&cnt2, g_cnt2);
    int *l3r, *l3c, *l2r, *l2c;
    float *l3v, *l2v;
    cudaGetSymbolAddress((void**)&l3r, g_l3_r);
    cudaGetSymbolAddress((void**)&l3c, g_l3_c);
    cudaGetSymbolAddress((void**)&l3v, g_l3_v);
    cudaGetSymbolAddress((void**)&l2r, g_l2_r);
    cudaGetSymbolAddress((void**)&l2c, g_l2_c);
    cudaGetSymbolAddress((void**)&l2v, g_l2_v);

    // 1. zero c1, c2, bitmaps, counters
    {
        unsigned n4 = (unsigned)N_CNT * DIM / 4;
        zero_main_kernel<<<(n4 + 255) / 256, 256>>>();
    }
    // 2. zero c3 at sampled rows + build S3/S2 seed
    prep_sampled_kernel<<<B_CNT, 128>>>(users, items);
    // 3. compact layer-3 edges, mark S2
    passB_kernel<<<(NNZ_CNT + 255) / 256, 256>>>(rows, cols, vals);
    // 4. compact layer-2 edges
    passC_kernel<<<(NNZ_CNT + 255) / 256, 256>>>(rows, cols, vals);

    // 5. layer 1 (full)
    {
        unsigned spmm_threads = (unsigned)NNZ_CNT * 16;
        spmm_first_kernel<<<(spmm_threads + 255) / 256, 256>>>(rows, cols, vals, ue, ie, c1);
    }
    // 6. layer 2 (filtered by S2)
    spmm_list_kernel<<<8192, 256>>>(l2r, l2c, l2v, cnt2, c1, c2);
    // 7. layer 3 (filtered by S3)
    spmm_list_kernel<<<8192, 256>>>(l3r, l3c, l3v, cnt3, c2, c3);

    // 8. epilogue
    finalize_kernel<<<B_CNT, 128>>>(ue, ie, W, bias, users, items, u_his, i_his, out);
}